// round 1
// baseline (speedup 1.0000x reference)
#include <cuda_runtime.h>

#define NN 100000
#define EE 1600000
#define HH 128
#define LL 3
#define GG 512
#define LAT 64
#define SLOPE 0.2f
#define BN_EPS 1e-5f

// ---------------- device scratch (static: no allocations allowed) ----------------
__device__ float g_h[NN * HH];     // node features after each layer
__device__ float g_s[NN * HH];     // h + aggregated neighbors
__device__ float g_t[NN * HH];     // intermediate MLP activation
__device__ int   g_deg[NN];
__device__ int   g_incl[NN];
__device__ int   g_rs[NN + 1];     // CSR row starts (by dst)
__device__ int   g_cur[NN];        // scatter cursors
__device__ int   g_col[EE];        // CSR columns (src ids)
__device__ int   g_bsum[128];
__device__ int   g_boff[129];
__device__ int   g_gcnt[GG];
__device__ int   g_gst[GG + 1];    // per-graph node ranges (batch is sorted)
__device__ float g_a1[LL * HH];    // folded BN scale per layer
__device__ float g_c1[LL * HH];    // folded BN shift per layer
__device__ float g_ap[HH];         // folded pooled-BN scale
__device__ float g_cp[HH];         // folded pooled-BN shift

// ---------------- small setup kernels ----------------
__global__ void k_zero() {
    int i = blockIdx.x * blockDim.x + threadIdx.x;
    if (i < NN) g_deg[i] = 0;
    if (i < GG) g_gcnt[i] = 0;
}

__global__ void k_fold(const float* __restrict__ g1, const float* __restrict__ beta1,
                       const float* __restrict__ rm1, const float* __restrict__ rv1,
                       const float* __restrict__ bng, const float* __restrict__ bnb,
                       const float* __restrict__ bnrm, const float* __restrict__ bnrv) {
    int i = threadIdx.x;  // 512 threads, 1 block
    if (i < LL * HH) {
        float a = g1[i] * rsqrtf(rv1[i] + BN_EPS);
        g_a1[i] = a;
        g_c1[i] = beta1[i] - a * rm1[i];
    }
    if (i < HH) {
        float a = bng[i] * rsqrtf(bnrv[i] + BN_EPS);
        g_ap[i] = a;
        g_cp[i] = bnb[i] - a * bnrm[i];
    }
}

__global__ void k_hist_deg(const int* __restrict__ dst) {
    int i = blockIdx.x * blockDim.x + threadIdx.x;
    if (i < EE) atomicAdd(&g_deg[dst[i]], 1);
}

__global__ void k_hist_batch(const int* __restrict__ batch) {
    int i = blockIdx.x * blockDim.x + threadIdx.x;
    if (i < NN) atomicAdd(&g_gcnt[batch[i]], 1);
}

// level-1 inclusive scan of g_deg, 1024 elems/block
__global__ void k_scan1() {
    __shared__ int sm[1024];
    int t = threadIdx.x;
    int i = blockIdx.x * 1024 + t;
    int v = (i < NN) ? g_deg[i] : 0;
    sm[t] = v;
    __syncthreads();
    for (int off = 1; off < 1024; off <<= 1) {
        int u = (t >= off) ? sm[t - off] : 0;
        __syncthreads();
        sm[t] += u;
        __syncthreads();
    }
    if (i < NN) g_incl[i] = sm[t];
    if (t == 1023) g_bsum[blockIdx.x] = sm[1023];
}

// exclusive scan of the 98 block sums
__global__ void k_scan_bsum() {
    __shared__ int sm[128];
    int t = threadIdx.x;  // 128 threads
    const int nb = (NN + 1023) / 1024;
    int v = (t < nb) ? g_bsum[t] : 0;
    sm[t] = v;
    __syncthreads();
    for (int off = 1; off < 128; off <<= 1) {
        int u = (t >= off) ? sm[t - off] : 0;
        __syncthreads();
        sm[t] += u;
        __syncthreads();
    }
    g_boff[t] = sm[t] - v;
}

__global__ void k_finalize_rs() {
    int i = blockIdx.x * blockDim.x + threadIdx.x;
    if (i < NN) {
        int incl = g_incl[i] + g_boff[i >> 10];
        g_rs[i + 1] = incl;
        g_cur[i] = incl - g_deg[i];  // exclusive start = scatter cursor
    }
    if (i == 0) g_rs[0] = 0;
}

__global__ void k_scatter(const int* __restrict__ src, const int* __restrict__ dst) {
    int e = blockIdx.x * blockDim.x + threadIdx.x;
    if (e < EE) {
        int p = atomicAdd(&g_cur[dst[e]], 1);
        g_col[p] = src[e];
    }
}

// exclusive scan of per-graph node counts (single block, G=512)
__global__ void k_scan_batch() {
    __shared__ int sm[GG];
    int t = threadIdx.x;  // 512 threads
    int v = g_gcnt[t];
    sm[t] = v;
    __syncthreads();
    for (int off = 1; off < GG; off <<= 1) {
        int u = (t >= off) ? sm[t - off] : 0;
        __syncthreads();
        sm[t] += u;
        __syncthreads();
    }
    g_gst[t + 1] = sm[t];
    if (t == 0) g_gst[0] = 0;
}

// ---------------- aggregation: s[i] = h[i] + sum_{j in N(i)} h[j] ----------------
__global__ void __launch_bounds__(128) k_agg(const float* __restrict__ x, int layer) {
    const float* __restrict__ hin = (layer == 0) ? x : (const float*)g_h;
    int node = blockIdx.x;
    int t = threadIdx.x;
    int beg = g_rs[node], end = g_rs[node + 1];
    float acc = hin[node * HH + t];
    __shared__ int idx[128];
    for (int j = beg; j < end; j += 128) {
        int cnt = min(128, end - j);
        if (t < cnt) idx[t] = g_col[j + t];
        __syncthreads();
        int u = 0;
        for (; u + 4 <= cnt; u += 4) {
            float v0 = hin[idx[u] * HH + t];
            float v1 = hin[idx[u + 1] * HH + t];
            float v2 = hin[idx[u + 2] * HH + t];
            float v3 = hin[idx[u + 3] * HH + t];
            acc += (v0 + v1) + (v2 + v3);
        }
        for (; u < cnt; u++) acc += hin[idx[u] * HH + t];
        __syncthreads();
    }
    g_s[node * HH + t] = acc;
}

// ---------------- GEMM: Out[N,128] = epi(S[N,128] @ W[128,128] + b) -------------
// phase 0: S=g_s -> Out=g_t, epi = affine(leaky(v))   (MLP half 1 + BN fold)
// phase 1: S=g_t -> Out=g_h, epi = leaky(v)           (MLP half 2)
__global__ void __launch_bounds__(256, 1) k_gemm(const float* __restrict__ W,
                                                 const float* __restrict__ bias,
                                                 int l, int phase) {
    extern __shared__ float smem[];
    float* Ws = smem;                 // 128*128
    float* As = smem + 128 * 128;     // 128*132 (padded rows)
    const float* __restrict__ S = phase ? (const float*)g_t : (const float*)g_s;
    float* __restrict__ O = phase ? g_h : g_t;

    int tid = threadIdx.x;
    int m0 = blockIdx.x * 128;

    const float4* W4 = (const float4*)W;
    float4* Ws4 = (float4*)Ws;
#pragma unroll
    for (int i = 0; i < 16; i++) Ws4[tid + i * 256] = W4[tid + i * 256];

#pragma unroll
    for (int i = 0; i < 16; i++) {
        int f = tid + i * 256;        // 0..4095 float4s
        int r = f >> 5, c4 = f & 31;
        int row = m0 + r;
        float4 v = (row < NN) ? ((const float4*)S)[row * 32 + c4]
                              : make_float4(0.f, 0.f, 0.f, 0.f);
        *(float4*)&As[r * 132 + c4 * 4] = v;
    }
    __syncthreads();

    int tx = tid & 15, ty = tid >> 4;
    unsigned long long acc[8][4];
#pragma unroll
    for (int i = 0; i < 8; i++)
#pragma unroll
        for (int j = 0; j < 4; j++) acc[i][j] = 0ull;

#pragma unroll 4
    for (int k = 0; k < 128; k++) {
        ulonglong2 b01 = *(const ulonglong2*)&Ws[k * 128 + tx * 8];
        ulonglong2 b23 = *(const ulonglong2*)&Ws[k * 128 + tx * 8 + 4];
#pragma unroll
        for (int i = 0; i < 8; i++) {
            float a = As[(ty * 8 + i) * 132 + k];
            unsigned long long ad;
            asm("mov.b64 %0,{%1,%1};" : "=l"(ad) : "f"(a));
            asm("fma.rn.f32x2 %0,%1,%2,%0;" : "+l"(acc[i][0]) : "l"(ad), "l"(b01.x));
            asm("fma.rn.f32x2 %0,%1,%2,%0;" : "+l"(acc[i][1]) : "l"(ad), "l"(b01.y));
            asm("fma.rn.f32x2 %0,%1,%2,%0;" : "+l"(acc[i][2]) : "l"(ad), "l"(b23.x));
            asm("fma.rn.f32x2 %0,%1,%2,%0;" : "+l"(acc[i][3]) : "l"(ad), "l"(b23.y));
        }
    }

    float bb[8], aa[8], cc[8];
#pragma unroll
    for (int j = 0; j < 8; j++) {
        int col = tx * 8 + j;
        bb[j] = bias[col];
        aa[j] = 1.f; cc[j] = 0.f;
        if (phase == 0) { aa[j] = g_a1[l * HH + col]; cc[j] = g_c1[l * HH + col]; }
    }
#pragma unroll
    for (int i = 0; i < 8; i++) {
        int row = m0 + ty * 8 + i;
        if (row < NN) {
            float o[8];
#pragma unroll
            for (int j = 0; j < 4; j++) {
                float lo, hi;
                asm("mov.b64 {%0,%1},%2;" : "=f"(lo), "=f"(hi) : "l"(acc[i][j]));
                o[2 * j] = lo; o[2 * j + 1] = hi;
            }
#pragma unroll
            for (int j = 0; j < 8; j++) {
                float v = o[j] + bb[j];
                v = v > 0.f ? v : SLOPE * v;
                if (phase == 0) v = aa[j] * v + cc[j];
                o[j] = v;
            }
            *(float4*)&O[row * HH + tx * 8]     = make_float4(o[0], o[1], o[2], o[3]);
            *(float4*)&O[row * HH + tx * 8 + 4] = make_float4(o[4], o[5], o[6], o[7]);
        }
    }
}

// ---------------- pooling + pooled-BN + FC ----------------
__global__ void __launch_bounds__(128) k_pool(const float* __restrict__ fcW,
                                              const float* __restrict__ fcb,
                                              float* __restrict__ out) {
    int g = blockIdx.x, t = threadIdx.x;
    int beg = g_gst[g], end = g_gst[g + 1];
    float acc = 0.f;
    int i = beg;
    for (; i + 4 <= end; i += 4) {
        float v0 = g_h[i * HH + t];
        float v1 = g_h[(i + 1) * HH + t];
        float v2 = g_h[(i + 2) * HH + t];
        float v3 = g_h[(i + 3) * HH + t];
        acc += (v0 + v1) + (v2 + v3);
    }
    for (; i < end; i++) acc += g_h[i * HH + t];
    acc = g_ap[t] * acc + g_cp[t];
    __shared__ float p[128];
    p[t] = acc;
    __syncthreads();
    if (t < LAT) {
        float o = fcb[t];
#pragma unroll 4
        for (int k = 0; k < HH; k++) o += p[k] * fcW[k * LAT + t];
        out[g * LAT + t] = o;
    }
}

// ---------------- launcher ----------------
extern "C" void kernel_launch(void* const* d_in, const int* in_sizes, int n_in,
                              void* d_out, int out_size) {
    const float* x     = (const float*)d_in[0];
    const int*   ei    = (const int*)d_in[1];
    const int*   batch = (const int*)d_in[2];
    const float* W1    = (const float*)d_in[3];
    const float* b1    = (const float*)d_in[4];
    const float* g1    = (const float*)d_in[5];
    const float* beta1 = (const float*)d_in[6];
    const float* rm1   = (const float*)d_in[7];
    const float* rv1   = (const float*)d_in[8];
    const float* W2    = (const float*)d_in[9];
    const float* b2    = (const float*)d_in[10];
    const float* bng   = (const float*)d_in[11];
    const float* bnb   = (const float*)d_in[12];
    const float* bnrm  = (const float*)d_in[13];
    const float* bnrv  = (const float*)d_in[14];
    const float* fcW   = (const float*)d_in[15];
    const float* fcb   = (const float*)d_in[16];
    float* out = (float*)d_out;
    const int* src = ei;
    const int* dst = ei + EE;

    const int smem = (128 * 128 + 128 * 132) * (int)sizeof(float);  // 133120 B
    cudaFuncSetAttribute(k_gemm, cudaFuncAttributeMaxDynamicSharedMemorySize, smem);

    k_zero<<<(NN + 255) / 256, 256>>>();
    k_fold<<<1, 512>>>(g1, beta1, rm1, rv1, bng, bnb, bnrm, bnrv);
    k_hist_deg<<<(EE + 255) / 256, 256>>>(dst);
    k_hist_batch<<<(NN + 255) / 256, 256>>>(batch);
    k_scan1<<<(NN + 1023) / 1024, 1024>>>();
    k_scan_bsum<<<1, 128>>>();
    k_finalize_rs<<<(NN + 255) / 256, 256>>>();
    k_scan_batch<<<1, GG>>>();
    k_scatter<<<(EE + 255) / 256, 256>>>(src, dst);

    const int gb = (NN + 127) / 128;
    for (int l = 0; l < LL; l++) {
        k_agg<<<NN, 128>>>(x, l);
        k_gemm<<<gb, 256, smem>>>(W1 + l * HH * HH, b1 + l * HH, l, 0);
        k_gemm<<<gb, 256, smem>>>(W2 + l * HH * HH, b2 + l * HH, l, 1);
    }
    k_pool<<<GG, 128>>>(fcW, fcb, out);
}

// round 3
// speedup vs baseline: 1.4582x; 1.4582x over previous
#include <cuda_runtime.h>
#include <cstdint>

#define NN 100000
#define EE 1600000
#define HH 128
#define LL 3
#define GG 512
#define LAT 64
#define SLOPE 0.2f
#define BN_EPS 1e-5f

// ---------------- device scratch ----------------
__device__ float g_h[NN * HH];
__device__ float g_s[NN * HH];
__device__ float g_t[NN * HH];
__device__ int   g_deg[NN];
__device__ int   g_incl[NN];
__device__ int   g_rs[NN + 1];
__device__ int   g_cur[NN];
__device__ int   g_col[EE];
__device__ int   g_bsum[128];
__device__ int   g_boff[129];
__device__ int   g_gst[GG + 1];
__device__ float g_a1[LL * HH];
__device__ float g_c1[LL * HH];
__device__ float g_ap[HH];
__device__ float g_cp[HH];
// per-matrix fragment-packed bf16 weights: [hi: 4096 uint2][lo: 4096 uint2] = 64KB
__device__ uint2 g_wb[6 * 8192];

// ---------------- helpers ----------------
// pack float2 (x=low col, y=high col) -> bf16x2 hi + bf16x2 lo(residual)
__device__ __forceinline__ void split2(float2 v, uint32_t& hi, uint32_t& lo) {
    asm("cvt.rn.bf16x2.f32 %0,%1,%2;" : "=r"(hi) : "f"(v.y), "f"(v.x));
    float r0 = v.x - __uint_as_float(hi << 16);
    float r1 = v.y - __uint_as_float(hi & 0xffff0000u);
    asm("cvt.rn.bf16x2.f32 %0,%1,%2;" : "=r"(lo) : "f"(r1), "f"(r0));
}

__device__ __forceinline__ void mma_bf16(float* d, const uint4& a, const uint2& b) {
    asm volatile(
        "mma.sync.aligned.m16n8k16.row.col.f32.bf16.bf16.f32 "
        "{%0,%1,%2,%3},{%4,%5,%6,%7},{%8,%9},{%0,%1,%2,%3};"
        : "+f"(d[0]), "+f"(d[1]), "+f"(d[2]), "+f"(d[3])
        : "r"(a.x), "r"(a.y), "r"(a.z), "r"(a.w), "r"(b.x), "r"(b.y));
}

// ---------------- setup kernels ----------------
__global__ void k_zero() {
    int i = blockIdx.x * blockDim.x + threadIdx.x;
    if (i < NN) g_deg[i] = 0;
}

__global__ void k_gst(const int* __restrict__ batch,
                      const float* __restrict__ g1, const float* __restrict__ beta1,
                      const float* __restrict__ rm1, const float* __restrict__ rv1,
                      const float* __restrict__ bng, const float* __restrict__ bnb,
                      const float* __restrict__ bnrm, const float* __restrict__ bnrv) {
    int t = threadIdx.x;  // 512
    if (t < LL * HH) {
        float a = g1[t] * rsqrtf(rv1[t] + BN_EPS);
        g_a1[t] = a;
        g_c1[t] = beta1[t] - a * rm1[t];
    }
    if (t < HH) {
        float a = bng[t] * rsqrtf(bnrv[t] + BN_EPS);
        g_ap[t] = a;
        g_cp[t] = bnb[t] - a * bnrm[t];
    }
    int lo = 0, hi = NN;
    while (lo < hi) { int m = (lo + hi) >> 1; if (batch[m] < t) lo = m + 1; else hi = m; }
    g_gst[t] = lo;
    if (t == 0) g_gst[GG] = NN;
}

// weights -> fragment-packed bf16 hi/lo in global
// slot s (0..4095): nt=s>>8, ks=(s>>5)&7, lane=s&31
// b0 = W[k0][n],W[k0+1][n]; b1 = W[k0+8][n],W[k0+9][n]
// k0 = ks*16+(lane&3)*2 ; n = nt*8+(lane>>2)
__global__ void __launch_bounds__(256) k_wconv(const float* __restrict__ W1,
                                               const float* __restrict__ W2) {
    int mat = blockIdx.x;  // 0..5
    int l = mat >> 1, ph = mat & 1;
    const float* w = (ph ? W2 : W1) + l * HH * HH;
    uint2* outh = &g_wb[mat * 8192];
    uint2* outl = outh + 4096;
    int tid = threadIdx.x;
#pragma unroll
    for (int i = 0; i < 16; i++) {
        int s = tid + i * 256;
        int nt = s >> 8, ks = (s >> 5) & 7, lane = s & 31;
        int k0 = ks * 16 + (lane & 3) * 2;
        int n = nt * 8 + (lane >> 2);
        float2 p0 = make_float2(w[k0 * HH + n], w[(k0 + 1) * HH + n]);
        float2 p1 = make_float2(w[(k0 + 8) * HH + n], w[(k0 + 9) * HH + n]);
        uint32_t h0, l0, h1, l1;
        split2(p0, h0, l0);
        split2(p1, h1, l1);
        outh[s] = make_uint2(h0, h1);
        outl[s] = make_uint2(l0, l1);
    }
}

__global__ void k_hist_deg(const int* __restrict__ dst) {
    int i = blockIdx.x * blockDim.x + threadIdx.x;
    if (i < EE) atomicAdd(&g_deg[dst[i]], 1);
}

__global__ void k_scan1() {
    __shared__ int sm[1024];
    int t = threadIdx.x;
    int i = blockIdx.x * 1024 + t;
    int v = (i < NN) ? g_deg[i] : 0;
    sm[t] = v;
    __syncthreads();
    for (int off = 1; off < 1024; off <<= 1) {
        int u = (t >= off) ? sm[t - off] : 0;
        __syncthreads();
        sm[t] += u;
        __syncthreads();
    }
    if (i < NN) g_incl[i] = sm[t];
    if (t == 1023) g_bsum[blockIdx.x] = sm[1023];
}

__global__ void k_scan_bsum() {
    __shared__ int sm[128];
    int t = threadIdx.x;
    const int nb = (NN + 1023) / 1024;
    int v = (t < nb) ? g_bsum[t] : 0;
    sm[t] = v;
    __syncthreads();
    for (int off = 1; off < 128; off <<= 1) {
        int u = (t >= off) ? sm[t - off] : 0;
        __syncthreads();
        sm[t] += u;
        __syncthreads();
    }
    g_boff[t] = sm[t] - v;
}

__global__ void k_finalize_rs() {
    int i = blockIdx.x * blockDim.x + threadIdx.x;
    if (i < NN) {
        int incl = g_incl[i] + g_boff[i >> 10];
        g_rs[i + 1] = incl;
        g_cur[i] = incl - g_deg[i];
    }
    if (i == 0) g_rs[0] = 0;
}

__global__ void k_scatter(const int* __restrict__ src, const int* __restrict__ dst) {
    int e = blockIdx.x * blockDim.x + threadIdx.x;
    if (e < EE) {
        int p = atomicAdd(&g_cur[dst[e]], 1);
        g_col[p] = src[e];
    }
}

// ---------------- aggregation: warp per node ----------------
__global__ void __launch_bounds__(256) k_agg(const float* __restrict__ x, int layer) {
    const float4* __restrict__ hin =
        (const float4*)((layer == 0) ? x : (const float*)g_h);
    int w = threadIdx.x >> 5, lane = threadIdx.x & 31;
    int node = blockIdx.x * 8 + w;
    if (node >= NN) return;
    int beg = g_rs[node], end = g_rs[node + 1];
    float4 a = hin[node * 32 + lane];
    for (int j = beg; j < end; j += 32) {
        int cnt = min(32, end - j);
        int idx = (lane < cnt) ? g_col[j + lane] : 0;
        int u = 0;
        for (; u + 4 <= cnt; u += 4) {
            int j0 = __shfl_sync(0xffffffffu, idx, u);
            int j1 = __shfl_sync(0xffffffffu, idx, u + 1);
            int j2 = __shfl_sync(0xffffffffu, idx, u + 2);
            int j3 = __shfl_sync(0xffffffffu, idx, u + 3);
            float4 v0 = hin[j0 * 32 + lane];
            float4 v1 = hin[j1 * 32 + lane];
            float4 v2 = hin[j2 * 32 + lane];
            float4 v3 = hin[j3 * 32 + lane];
            a.x += (v0.x + v1.x) + (v2.x + v3.x);
            a.y += (v0.y + v1.y) + (v2.y + v3.y);
            a.z += (v0.z + v1.z) + (v2.z + v3.z);
            a.w += (v0.w + v1.w) + (v2.w + v3.w);
        }
        for (; u < cnt; u++) {
            int jj = __shfl_sync(0xffffffffu, idx, u);
            float4 v = hin[jj * 32 + lane];
            a.x += v.x; a.y += v.y; a.z += v.z; a.w += v.w;
        }
    }
    ((float4*)g_s)[node * 32 + lane] = a;
}

// ---------------- HMMA GEMM: Out[128-tile,128] = epi(S@W + b) ----------------
// smem: As_hi uint4[2048] @0 (32KB), As_lo @32KB, Bs_hi uint2[4096] @64KB, Bs_lo @96KB
__global__ void __launch_bounds__(256) k_mma(const float* __restrict__ bias,
                                             int l, int phase) {
    extern __shared__ char sm[];
    uint4* As_h = (uint4*)sm;
    uint4* As_l = (uint4*)(sm + 32768);
    uint2* Bs_h = (uint2*)(sm + 65536);
    uint2* Bs_l = (uint2*)(sm + 98304);

    const float* __restrict__ S = phase ? (const float*)g_t : (const float*)g_s;
    float* __restrict__ O = phase ? g_h : g_t;

    int tid = threadIdx.x, wid = tid >> 5, lane = tid & 31;
    int warp_m = wid >> 2, warp_n = wid & 3;
    int m0 = blockIdx.x * 128;

    // B: vector copy of preconverted fragment image (hi then lo, contiguous 64KB)
    {
        const uint4* src = (const uint4*)&g_wb[(l * 2 + phase) * 8192];
        uint4* dst = (uint4*)Bs_h;  // Bs_h and Bs_l are contiguous
#pragma unroll
        for (int i = 0; i < 16; i++) dst[tid + i * 256] = src[tid + i * 256];
    }

    // A: fp32 -> bf16 hi/lo, fragment-packed
    const float2* __restrict__ S2 = (const float2*)S;
#pragma unroll
    for (int i = 0; i < 8; i++) {
        int s = tid + i * 256;               // 0..2047
        int mt = s >> 8, ks = (s >> 5) & 7, ln = s & 31;
        int r = m0 + mt * 16 + (ln >> 2);
        int cp = ks * 8 + (ln & 3);          // float2 index (col pair)
        float2 z = make_float2(0.f, 0.f);
        float2 p0 = (r < NN)     ? S2[r * 64 + cp]           : z;
        float2 p1 = (r + 8 < NN) ? S2[(r + 8) * 64 + cp]     : z;
        float2 p2 = (r < NN)     ? S2[r * 64 + cp + 4]       : z;
        float2 p3 = (r + 8 < NN) ? S2[(r + 8) * 64 + cp + 4] : z;
        uint4 hi, lo;
        split2(p0, hi.x, lo.x);
        split2(p1, hi.y, lo.y);
        split2(p2, hi.z, lo.z);
        split2(p3, hi.w, lo.w);
        As_h[s] = hi;
        As_l[s] = lo;
    }
    __syncthreads();

    float d[4][4][4];
#pragma unroll
    for (int mt = 0; mt < 4; mt++)
#pragma unroll
        for (int nt = 0; nt < 4; nt++)
#pragma unroll
            for (int q = 0; q < 4; q++) d[mt][nt][q] = 0.f;

#pragma unroll 1
    for (int ks = 0; ks < 8; ks++) {
        uint4 ah[4], al[4];
#pragma unroll
        for (int mt = 0; mt < 4; mt++) {
            int sa = ((warp_m * 4 + mt) * 8 + ks) * 32 + lane;
            ah[mt] = As_h[sa];
            al[mt] = As_l[sa];
        }
#pragma unroll
        for (int nt = 0; nt < 4; nt++) {
            int sb = ((warp_n * 4 + nt) * 8 + ks) * 32 + lane;
            uint2 bh = Bs_h[sb];
            uint2 bl = Bs_l[sb];
#pragma unroll
            for (int mt = 0; mt < 4; mt++) {
                mma_bf16(d[mt][nt], ah[mt], bh);
                mma_bf16(d[mt][nt], ah[mt], bl);
                mma_bf16(d[mt][nt], al[mt], bh);
            }
        }
    }

    // epilogue: bias + leaky + (phase0: BN affine)
#pragma unroll
    for (int nt = 0; nt < 4; nt++) {
        int c0 = warp_n * 32 + nt * 8 + (lane & 3) * 2;
        float bb0 = bias[c0], bb1 = bias[c0 + 1];
        float aa0 = 1.f, aa1 = 1.f, cc0 = 0.f, cc1 = 0.f;
        if (phase == 0) {
            aa0 = g_a1[l * HH + c0];     cc0 = g_c1[l * HH + c0];
            aa1 = g_a1[l * HH + c0 + 1]; cc1 = g_c1[l * HH + c0 + 1];
        }
#pragma unroll
        for (int mt = 0; mt < 4; mt++) {
            int r = m0 + warp_m * 64 + mt * 16 + (lane >> 2);
            float v0 = d[mt][nt][0] + bb0, v1 = d[mt][nt][1] + bb1;
            float v2 = d[mt][nt][2] + bb0, v3 = d[mt][nt][3] + bb1;
            v0 = v0 > 0.f ? v0 : SLOPE * v0;
            v1 = v1 > 0.f ? v1 : SLOPE * v1;
            v2 = v2 > 0.f ? v2 : SLOPE * v2;
            v3 = v3 > 0.f ? v3 : SLOPE * v3;
            if (phase == 0) {
                v0 = aa0 * v0 + cc0; v1 = aa1 * v1 + cc1;
                v2 = aa0 * v2 + cc0; v3 = aa1 * v3 + cc1;
            }
            if (r < NN)     *(float2*)&O[r * HH + c0]       = make_float2(v0, v1);
            if (r + 8 < NN) *(float2*)&O[(r + 8) * HH + c0] = make_float2(v2, v3);
        }
    }
}

// ---------------- pooling + pooled-BN + FC ----------------
__global__ void __launch_bounds__(128) k_pool(const float* __restrict__ fcW,
                                              const float* __restrict__ fcb,
                                              float* __restrict__ out) {
    int g = blockIdx.x, t = threadIdx.x;
    int beg = g_gst[g], end = g_gst[g + 1];
    float acc = 0.f;
    int i = beg;
    for (; i + 4 <= end; i += 4) {
        float v0 = g_h[i * HH + t];
        float v1 = g_h[(i + 1) * HH + t];
        float v2 = g_h[(i + 2) * HH + t];
        float v3 = g_h[(i + 3) * HH + t];
        acc += (v0 + v1) + (v2 + v3);
    }
    for (; i < end; i++) acc += g_h[i * HH + t];
    acc = g_ap[t] * acc + g_cp[t];
    __shared__ float p[128];
    p[t] = acc;
    __syncthreads();
    if (t < LAT) {
        float o = fcb[t];
#pragma unroll 4
        for (int k = 0; k < HH; k++) o += p[k] * fcW[k * LAT + t];
        out[g * LAT + t] = o;
    }
}

// ---------------- launcher ----------------
extern "C" void kernel_launch(void* const* d_in, const int* in_sizes, int n_in,
                              void* d_out, int out_size) {
    const float* x     = (const float*)d_in[0];
    const int*   ei    = (const int*)d_in[1];
    const int*   batch = (const int*)d_in[2];
    const float* W1    = (const float*)d_in[3];
    const float* b1    = (const float*)d_in[4];
    const float* g1    = (const float*)d_in[5];
    const float* beta1 = (const float*)d_in[6];
    const float* rm1   = (const float*)d_in[7];
    const float* rv1   = (const float*)d_in[8];
    const float* W2    = (const float*)d_in[9];
    const float* b2    = (const float*)d_in[10];
    const float* bng   = (const float*)d_in[11];
    const float* bnb   = (const float*)d_in[12];
    const float* bnrm  = (const float*)d_in[13];
    const float* bnrv  = (const float*)d_in[14];
    const float* fcW   = (const float*)d_in[15];
    const float* fcb   = (const float*)d_in[16];
    float* out = (float*)d_out;
    const int* src = ei;
    const int* dst = ei + EE;

    const int smem = 131072;
    cudaFuncSetAttribute(k_mma, cudaFuncAttributeMaxDynamicSharedMemorySize, smem);

    k_zero<<<(NN + 255) / 256, 256>>>();
    k_gst<<<1, 512>>>(batch, g1, beta1, rm1, rv1, bng, bnb, bnrm, bnrv);
    k_wconv<<<6, 256>>>(W1, W2);
    k_hist_deg<<<(EE + 255) / 256, 256>>>(dst);
    k_scan1<<<(NN + 1023) / 1024, 1024>>>();
    k_scan_bsum<<<1, 128>>>();
    k_finalize_rs<<<(NN + 255) / 256, 256>>>();
    k_scatter<<<(EE + 255) / 256, 256>>>(src, dst);

    const int gb = (NN + 127) / 128;   // 782
    for (int l = 0; l < LL; l++) {
        k_agg<<<(NN + 7) / 8, 256>>>(x, l);
        k_mma<<<gb, 256, smem>>>(b1 + l * HH, l, 0);
        k_mma<<<gb, 256, smem>>>(b2 + l * HH, l, 1);
    }
    k_pool<<<GG, 128>>>(fcW, fcb, out);
}

// round 4
// speedup vs baseline: 1.6982x; 1.1645x over previous
#include <cuda_runtime.h>
#include <cuda_fp16.h>
#include <cstdint>

#define NN 100000
#define EE 1600000
#define HH 128
#define LL 3
#define GG 512
#define LAT 64
#define SLOPE 0.2f
#define BN_EPS 1e-5f

// ---------------- device scratch ----------------
__device__ float g_h[NN * HH];
__device__ float g_s[NN * HH];
__device__ uint2 g_h16[NN * 32];   // fp16 mirror of h (4 halves per uint2)
__device__ uint2 g_x16[NN * 32];   // fp16 mirror of x
__device__ int   g_deg[NN];
__device__ int   g_incl[NN];
__device__ int   g_rs[NN + 1];
__device__ int   g_cur[NN];
__device__ int   g_col[EE];
__device__ int   g_bsum[128];
__device__ int   g_boff[129];
__device__ int   g_gst[GG + 1];
__device__ float g_a1[LL * HH];
__device__ float g_c1[LL * HH];
__device__ float g_ap[HH];
__device__ float g_cp[HH];
// per-matrix fragment-packed bf16 weights: [hi: 4096 uint2][lo: 4096 uint2] = 64KB
__device__ uint2 g_wb[6 * 8192];

// ---------------- helpers ----------------
__device__ __forceinline__ void split2(float2 v, uint32_t& hi, uint32_t& lo) {
    asm("cvt.rn.bf16x2.f32 %0,%1,%2;" : "=r"(hi) : "f"(v.y), "f"(v.x));
    float r0 = v.x - __uint_as_float(hi << 16);
    float r1 = v.y - __uint_as_float(hi & 0xffff0000u);
    asm("cvt.rn.bf16x2.f32 %0,%1,%2;" : "=r"(lo) : "f"(r1), "f"(r0));
}

__device__ __forceinline__ void mma_bf16(float* d, const uint4& a, const uint2& b) {
    asm volatile(
        "mma.sync.aligned.m16n8k16.row.col.f32.bf16.bf16.f32 "
        "{%0,%1,%2,%3},{%4,%5,%6,%7},{%8,%9},{%0,%1,%2,%3};"
        : "+f"(d[0]), "+f"(d[1]), "+f"(d[2]), "+f"(d[3])
        : "r"(a.x), "r"(a.y), "r"(a.z), "r"(a.w), "r"(b.x), "r"(b.y));
}

// ---------------- merged setup kernel ----------------
// blocks [0,3200): x -> fp16 ; [3200,3591): zero deg ; [3591,3593): gst+BN fold ;
// [3593,3599): weight conversion
__global__ void __launch_bounds__(256) k_setup(
    const float* __restrict__ x, const int* __restrict__ batch,
    const float* __restrict__ g1, const float* __restrict__ beta1,
    const float* __restrict__ rm1, const float* __restrict__ rv1,
    const float* __restrict__ bng, const float* __restrict__ bnb,
    const float* __restrict__ bnrm, const float* __restrict__ bnrv,
    const float* __restrict__ W1, const float* __restrict__ W2) {
    int b = blockIdx.x, tid = threadIdx.x;
    if (b < 3200) {
        const float4* x4 = (const float4*)x;
#pragma unroll
        for (int i = 0; i < 4; i++) {
            int idx = (b * 256 + tid) * 4 + i;
            if (idx < NN * 32) {
                float4 v = x4[idx];
                __half2 h0 = __float22half2_rn(make_float2(v.x, v.y));
                __half2 h1 = __float22half2_rn(make_float2(v.z, v.w));
                g_x16[idx] = make_uint2(*(uint32_t*)&h0, *(uint32_t*)&h1);
            }
        }
    } else if (b < 3591) {
        int i = (b - 3200) * 256 + tid;
        if (i < NN) g_deg[i] = 0;
    } else if (b < 3593) {
        int t = (b - 3591) * 256 + tid;   // 0..511
        if (t < LL * HH) {
            float a = g1[t] * rsqrtf(rv1[t] + BN_EPS);
            g_a1[t] = a;
            g_c1[t] = beta1[t] - a * rm1[t];
        }
        if (t < HH) {
            float a = bng[t] * rsqrtf(bnrv[t] + BN_EPS);
            g_ap[t] = a;
            g_cp[t] = bnb[t] - a * bnrm[t];
        }
        int lo = 0, hi = NN;
        while (lo < hi) { int m = (lo + hi) >> 1; if (batch[m] < t) lo = m + 1; else hi = m; }
        g_gst[t] = lo;
        if (t == 0) g_gst[GG] = NN;
    } else {
        int mat = b - 3593;   // 0..5
        int l = mat >> 1, ph = mat & 1;
        const float* w = (ph ? W2 : W1) + l * HH * HH;
        uint2* outh = &g_wb[mat * 8192];
        uint2* outl = outh + 4096;
#pragma unroll
        for (int i = 0; i < 16; i++) {
            int s = tid + i * 256;
            int nt = s >> 8, ks = (s >> 5) & 7, lane = s & 31;
            int k0 = ks * 16 + (lane & 3) * 2;
            int n = nt * 8 + (lane >> 2);
            float2 p0 = make_float2(w[k0 * HH + n], w[(k0 + 1) * HH + n]);
            float2 p1 = make_float2(w[(k0 + 8) * HH + n], w[(k0 + 9) * HH + n]);
            uint32_t h0, l0, h1, l1;
            split2(p0, h0, l0);
            split2(p1, h1, l1);
            outh[s] = make_uint2(h0, h1);
            outl[s] = make_uint2(l0, l1);
        }
    }
}

// ---------------- CSR build ----------------
__global__ void k_hist_deg(const int* __restrict__ dst) {
    int i = blockIdx.x * blockDim.x + threadIdx.x;
    if (i < EE) atomicAdd(&g_deg[dst[i]], 1);
}

__global__ void k_scan1() {
    __shared__ int sm[1024];
    int t = threadIdx.x;
    int i = blockIdx.x * 1024 + t;
    int v = (i < NN) ? g_deg[i] : 0;
    sm[t] = v;
    __syncthreads();
    for (int off = 1; off < 1024; off <<= 1) {
        int u = (t >= off) ? sm[t - off] : 0;
        __syncthreads();
        sm[t] += u;
        __syncthreads();
    }
    if (i < NN) g_incl[i] = sm[t];
    if (t == 1023) g_bsum[blockIdx.x] = sm[1023];
}

__global__ void k_scan_bsum() {
    __shared__ int sm[128];
    int t = threadIdx.x;
    const int nb = (NN + 1023) / 1024;
    int v = (t < nb) ? g_bsum[t] : 0;
    sm[t] = v;
    __syncthreads();
    for (int off = 1; off < 128; off <<= 1) {
        int u = (t >= off) ? sm[t - off] : 0;
        __syncthreads();
        sm[t] += u;
        __syncthreads();
    }
    g_boff[t] = sm[t] - v;
}

__global__ void k_finalize_rs() {
    int i = blockIdx.x * blockDim.x + threadIdx.x;
    if (i < NN) {
        int incl = g_incl[i] + g_boff[i >> 10];
        g_rs[i + 1] = incl;
        g_cur[i] = incl - g_deg[i];
    }
    if (i == 0) g_rs[0] = 0;
}

__global__ void k_scatter(const int* __restrict__ src, const int* __restrict__ dst) {
    int e = blockIdx.x * blockDim.x + threadIdx.x;
    if (e < EE) {
        int p = atomicAdd(&g_cur[dst[e]], 1);
        g_col[p] = src[e];
    }
}

// ---------------- aggregation: warp per node, fp16 gather + fp32 self ----------------
__global__ void __launch_bounds__(256) k_agg(const float* __restrict__ x, int layer) {
    const float4* __restrict__ self4 =
        (const float4*)((layer == 0) ? x : (const float*)g_h);
    const uint2* __restrict__ h16 = (layer == 0) ? g_x16 : g_h16;
    int w = threadIdx.x >> 5, lane = threadIdx.x & 31;
    int node = blockIdx.x * 8 + w;
    if (node >= NN) return;
    int beg = g_rs[node], end = g_rs[node + 1];
    float4 sf = self4[node * 32 + lane];
    float a0 = sf.x, a1 = sf.y, a2 = sf.z, a3 = sf.w;
    for (int j = beg; j < end; j += 32) {
        int cnt = min(32, end - j);
        int idx = (lane < cnt) ? g_col[j + lane] : 0;
        int u = 0;
        for (; u + 4 <= cnt; u += 4) {
            int j0 = __shfl_sync(0xffffffffu, idx, u);
            int j1 = __shfl_sync(0xffffffffu, idx, u + 1);
            int j2 = __shfl_sync(0xffffffffu, idx, u + 2);
            int j3 = __shfl_sync(0xffffffffu, idx, u + 3);
            uint2 v0 = h16[j0 * 32 + lane];
            uint2 v1 = h16[j1 * 32 + lane];
            uint2 v2 = h16[j2 * 32 + lane];
            uint2 v3 = h16[j3 * 32 + lane];
#pragma unroll
            for (int q = 0; q < 1; q++) {
                float2 f;
                f = __half22float2(*(__half2*)&v0.x); a0 += f.x; a1 += f.y;
                f = __half22float2(*(__half2*)&v0.y); a2 += f.x; a3 += f.y;
                f = __half22float2(*(__half2*)&v1.x); a0 += f.x; a1 += f.y;
                f = __half22float2(*(__half2*)&v1.y); a2 += f.x; a3 += f.y;
                f = __half22float2(*(__half2*)&v2.x); a0 += f.x; a1 += f.y;
                f = __half22float2(*(__half2*)&v2.y); a2 += f.x; a3 += f.y;
                f = __half22float2(*(__half2*)&v3.x); a0 += f.x; a1 += f.y;
                f = __half22float2(*(__half2*)&v3.y); a2 += f.x; a3 += f.y;
            }
        }
        for (; u < cnt; u++) {
            int jj = __shfl_sync(0xffffffffu, idx, u);
            uint2 v = h16[jj * 32 + lane];
            float2 f;
            f = __half22float2(*(__half2*)&v.x); a0 += f.x; a1 += f.y;
            f = __half22float2(*(__half2*)&v.y); a2 += f.x; a3 += f.y;
        }
    }
    ((float4*)g_s)[node * 32 + lane] = make_float4(a0, a1, a2, a3);
}

// ---------------- fused MLP: h = leaky(W2ᵀ·affine(leaky(W1ᵀ·s + b1)) + b2) ----------
// smem: As_h 32KB @0, As_l @32KB, B1 frags 64KB @64KB, B2 frags 64KB @128KB = 192KB.
// GEMM1 D-fragments convert in-register into GEMM2 A-fragments (identical layout),
// exchanged through the As region.
__global__ void __launch_bounds__(256) k_mlp(const float* __restrict__ b1,
                                             const float* __restrict__ b2, int l) {
    extern __shared__ char sm[];
    uint4* As_h = (uint4*)sm;
    uint4* As_l = (uint4*)(sm + 32768);
    uint2* Bs_h1 = (uint2*)(sm + 65536);
    uint2* Bs_l1 = (uint2*)(sm + 98304);
    uint2* Bs_h2 = (uint2*)(sm + 131072);
    uint2* Bs_l2 = (uint2*)(sm + 163840);

    int tid = threadIdx.x, wid = tid >> 5, lane = tid & 31;
    int warp_m = wid >> 2, warp_n = wid & 3;
    int m0 = blockIdx.x * 128;

    // copy both weight images (contiguous 128KB in g_wb)
    {
        const uint4* src = (const uint4*)&g_wb[l * 16384];
        uint4* dst = (uint4*)Bs_h1;
#pragma unroll
        for (int i = 0; i < 32; i++) dst[tid + i * 256] = src[tid + i * 256];
    }

    // A: fp32 -> bf16 hi/lo, fragment-packed
    const float2* __restrict__ S2 = (const float2*)g_s;
#pragma unroll
    for (int i = 0; i < 8; i++) {
        int s = tid + i * 256;
        int mt = s >> 8, ks = (s >> 5) & 7, ln = s & 31;
        int r = m0 + mt * 16 + (ln >> 2);
        int cp = ks * 8 + (ln & 3);
        float2 z = make_float2(0.f, 0.f);
        float2 p0 = (r < NN)     ? S2[r * 64 + cp]           : z;
        float2 p1 = (r + 8 < NN) ? S2[(r + 8) * 64 + cp]     : z;
        float2 p2 = (r < NN)     ? S2[r * 64 + cp + 4]       : z;
        float2 p3 = (r + 8 < NN) ? S2[(r + 8) * 64 + cp + 4] : z;
        uint4 hi, lo;
        split2(p0, hi.x, lo.x);
        split2(p1, hi.y, lo.y);
        split2(p2, hi.z, lo.z);
        split2(p3, hi.w, lo.w);
        As_h[s] = hi;
        As_l[s] = lo;
    }
    __syncthreads();

    float d[4][4][4];
#pragma unroll
    for (int mt = 0; mt < 4; mt++)
#pragma unroll
        for (int nt = 0; nt < 4; nt++)
#pragma unroll
            for (int q = 0; q < 4; q++) d[mt][nt][q] = 0.f;

    // ---- GEMM1 ----
#pragma unroll 1
    for (int ks = 0; ks < 8; ks++) {
        uint4 ah[4], al[4];
#pragma unroll
        for (int mt = 0; mt < 4; mt++) {
            int sa = ((warp_m * 4 + mt) * 8 + ks) * 32 + lane;
            ah[mt] = As_h[sa];
            al[mt] = As_l[sa];
        }
#pragma unroll
        for (int nt = 0; nt < 4; nt++) {
            int sb = ((warp_n * 4 + nt) * 8 + ks) * 32 + lane;
            uint2 bh = Bs_h1[sb];
            uint2 bl = Bs_l1[sb];
#pragma unroll
            for (int mt = 0; mt < 4; mt++) {
                mma_bf16(d[mt][nt], ah[mt], bh);
                mma_bf16(d[mt][nt], ah[mt], bl);
                mma_bf16(d[mt][nt], al[mt], bh);
            }
        }
    }

    // ---- epilogue1 + in-register conversion to GEMM2 A-fragments ----
    uint4 th[4][2], tl[4][2];
    {
        float aa[8], cc[8], bb[8];
#pragma unroll
        for (int j = 0; j < 8; j++) {
            int c = warp_n * 32 + (j >> 1) * 8 + (lane & 3) * 2 + (j & 1);
            bb[j] = b1[c];
            aa[j] = g_a1[l * HH + c];
            cc[j] = g_c1[l * HH + c];
        }
#pragma unroll
        for (int mt = 0; mt < 4; mt++) {
#pragma unroll
            for (int nt = 0; nt < 4; nt++) {
#pragma unroll
                for (int q = 0; q < 4; q++) {
                    float v = d[mt][nt][q] + bb[nt * 2 + (q & 1)];
                    v = v > 0.f ? v : SLOPE * v;
                    d[mt][nt][q] = aa[nt * 2 + (q & 1)] * v + cc[nt * 2 + (q & 1)];
                }
            }
#pragma unroll
            for (int kp = 0; kp < 2; kp++) {
                uint4 hi, lo;
                split2(make_float2(d[mt][2 * kp][0],     d[mt][2 * kp][1]),     hi.x, lo.x);
                split2(make_float2(d[mt][2 * kp][2],     d[mt][2 * kp][3]),     hi.y, lo.y);
                split2(make_float2(d[mt][2 * kp + 1][0], d[mt][2 * kp + 1][1]), hi.z, lo.z);
                split2(make_float2(d[mt][2 * kp + 1][2], d[mt][2 * kp + 1][3]), hi.w, lo.w);
                th[mt][kp] = hi;
                tl[mt][kp] = lo;
            }
        }
    }
    __syncthreads();   // everyone done reading As in GEMM1
#pragma unroll
    for (int mt = 0; mt < 4; mt++)
#pragma unroll
        for (int kp = 0; kp < 2; kp++) {
            int slot = ((warp_m * 4 + mt) * 8 + warp_n * 2 + kp) * 32 + lane;
            As_h[slot] = th[mt][kp];
            As_l[slot] = tl[mt][kp];
        }
    __syncthreads();

#pragma unroll
    for (int mt = 0; mt < 4; mt++)
#pragma unroll
        for (int nt = 0; nt < 4; nt++)
#pragma unroll
            for (int q = 0; q < 4; q++) d[mt][nt][q] = 0.f;

    // ---- GEMM2 ----
#pragma unroll 1
    for (int ks = 0; ks < 8; ks++) {
        uint4 ah[4], al[4];
#pragma unroll
        for (int mt = 0; mt < 4; mt++) {
            int sa = ((warp_m * 4 + mt) * 8 + ks) * 32 + lane;
            ah[mt] = As_h[sa];
            al[mt] = As_l[sa];
        }
#pragma unroll
        for (int nt = 0; nt < 4; nt++) {
            int sb = ((warp_n * 4 + nt) * 8 + ks) * 32 + lane;
            uint2 bh = Bs_h2[sb];
            uint2 bl = Bs_l2[sb];
#pragma unroll
            for (int mt = 0; mt < 4; mt++) {
                mma_bf16(d[mt][nt], ah[mt], bh);
                mma_bf16(d[mt][nt], ah[mt], bl);
                mma_bf16(d[mt][nt], al[mt], bh);
            }
        }
    }

    // ---- epilogue2: bias + leaky -> g_h fp32 + g_h16 fp16 ----
#pragma unroll
    for (int nt = 0; nt < 4; nt++) {
        int c0 = warp_n * 32 + nt * 8 + (lane & 3) * 2;
        float bb0 = b2[c0], bb1 = b2[c0 + 1];
#pragma unroll
        for (int mt = 0; mt < 4; mt++) {
            int r = m0 + warp_m * 64 + mt * 16 + (lane >> 2);
            float v0 = d[mt][nt][0] + bb0, v1 = d[mt][nt][1] + bb1;
            float v2 = d[mt][nt][2] + bb0, v3 = d[mt][nt][3] + bb1;
            v0 = v0 > 0.f ? v0 : SLOPE * v0;
            v1 = v1 > 0.f ? v1 : SLOPE * v1;
            v2 = v2 > 0.f ? v2 : SLOPE * v2;
            v3 = v3 > 0.f ? v3 : SLOPE * v3;
            if (r < NN) {
                *(float2*)&g_h[r * HH + c0] = make_float2(v0, v1);
                __half2 hh = __float22half2_rn(make_float2(v0, v1));
                ((uint32_t*)g_h16)[r * 64 + c0 / 2] = *(uint32_t*)&hh;
            }
            if (r + 8 < NN) {
                *(float2*)&g_h[(r + 8) * HH + c0] = make_float2(v2, v3);
                __half2 hh = __float22half2_rn(make_float2(v2, v3));
                ((uint32_t*)g_h16)[(r + 8) * 64 + c0 / 2] = *(uint32_t*)&hh;
            }
        }
    }
}

// ---------------- pooling + pooled-BN + FC ----------------
__global__ void __launch_bounds__(128) k_pool(const float* __restrict__ fcW,
                                              const float* __restrict__ fcb,
                                              float* __restrict__ out) {
    int g = blockIdx.x, t = threadIdx.x;
    int beg = g_gst[g], end = g_gst[g + 1];
    float acc = 0.f;
    int i = beg;
    for (; i + 4 <= end; i += 4) {
        float v0 = g_h[i * HH + t];
        float v1 = g_h[(i + 1) * HH + t];
        float v2 = g_h[(i + 2) * HH + t];
        float v3 = g_h[(i + 3) * HH + t];
        acc += (v0 + v1) + (v2 + v3);
    }
    for (; i < end; i++) acc += g_h[i * HH + t];
    acc = g_ap[t] * acc + g_cp[t];
    __shared__ float p[128];
    p[t] = acc;
    __syncthreads();
    if (t < LAT) {
        float o = fcb[t];
#pragma unroll 4
        for (int k = 0; k < HH; k++) o += p[k] * fcW[k * LAT + t];
        out[g * LAT + t] = o;
    }
}

// ---------------- launcher ----------------
extern "C" void kernel_launch(void* const* d_in, const int* in_sizes, int n_in,
                              void* d_out, int out_size) {
    const float* x     = (const float*)d_in[0];
    const int*   ei    = (const int*)d_in[1];
    const int*   batch = (const int*)d_in[2];
    const float* W1    = (const float*)d_in[3];
    const float* b1    = (const float*)d_in[4];
    const float* g1    = (const float*)d_in[5];
    const float* beta1 = (const float*)d_in[6];
    const float* rm1   = (const float*)d_in[7];
    const float* rv1   = (const float*)d_in[8];
    const float* W2    = (const float*)d_in[9];
    const float* b2    = (const float*)d_in[10];
    const float* bng   = (const float*)d_in[11];
    const float* bnb   = (const float*)d_in[12];
    const float* bnrm  = (const float*)d_in[13];
    const float* bnrv  = (const float*)d_in[14];
    const float* fcW   = (const float*)d_in[15];
    const float* fcb   = (const float*)d_in[16];
    float* out = (float*)d_out;
    const int* src = ei;
    const int* dst = ei + EE;

    const int smem = 196608;
    cudaFuncSetAttribute(k_mlp, cudaFuncAttributeMaxDynamicSharedMemorySize, smem);

    k_setup<<<3599, 256>>>(x, batch, g1, beta1, rm1, rv1, bng, bnb, bnrm, bnrv, W1, W2);
    k_hist_deg<<<(EE + 255) / 256, 256>>>(dst);
    k_scan1<<<(NN + 1023) / 1024, 1024>>>();
    k_scan_bsum<<<1, 128>>>();
    k_finalize_rs<<<(NN + 255) / 256, 256>>>();
    k_scatter<<<(EE + 255) / 256, 256>>>(src, dst);

    const int gb = (NN + 127) / 128;   // 782
    for (int l = 0; l < LL; l++) {
        k_agg<<<(NN + 7) / 8, 256>>>(x, l);
        k_mlp<<<gb, 256, smem>>>(b1 + l * HH, b2 + l * HH, l);
    }
    k_pool<<<GG, 128>>>(fcW, fcb, out);
}

// round 5
// speedup vs baseline: 2.9427x; 1.7328x over previous
#include <cuda_runtime.h>
#include <cuda_fp16.h>
#include <cstdint>

#define NN 100000
#define EE 1600000
#define HH 128
#define LL 3
#define GG 512
#define LAT 64
#define SLOPE 0.2f
#define BN_EPS 1e-5f

// ---------------- device scratch (all activations fp16) ----------------
__device__ uint2 g_x16[NN * 32];   // fp16 x
__device__ uint2 g_h16[NN * 32];   // fp16 h
__device__ uint2 g_s16[NN * 32];   // fp16 s = h + agg
__device__ int   g_deg[NN];
__device__ int   g_incl[NN];
__device__ int   g_rs[NN + 1];
__device__ int   g_cur[NN];
__device__ int   g_col[EE];
__device__ int   g_bsum[128];
__device__ int   g_boff[129];
__device__ int   g_gst[GG + 1];
__device__ float g_a1[LL * HH];
__device__ float g_c1[LL * HH];
__device__ float g_ap[HH];
__device__ float g_cp[HH];
__device__ uint2 g_wb[6 * 4096];   // fp16 fragment-packed weights, 32KB/matrix

// ---------------- helpers ----------------
__device__ __forceinline__ uint32_t packh2(float a, float b) {
    __half2 h = __float22half2_rn(make_float2(a, b));
    return *(uint32_t*)&h;
}

__device__ __forceinline__ void mma_f16(float* d, const uint4& a, const uint2& b) {
    asm volatile(
        "mma.sync.aligned.m16n8k16.row.col.f32.f16.f16.f32 "
        "{%0,%1,%2,%3},{%4,%5,%6,%7},{%8,%9},{%0,%1,%2,%3};"
        : "+f"(d[0]), "+f"(d[1]), "+f"(d[2]), "+f"(d[3])
        : "r"(a.x), "r"(a.y), "r"(a.z), "r"(a.w), "r"(b.x), "r"(b.y));
}

// ---------------- merged setup ----------------
// blocks [0,3200): x->fp16 ; [3200,3591): zero deg ; [3591,3593): BN fold + gst ;
// [3593,3599): weight conversion (fp16 fragments)
__global__ void __launch_bounds__(256) k_setup(
    const float* __restrict__ x, const int* __restrict__ batch,
    const float* __restrict__ g1, const float* __restrict__ beta1,
    const float* __restrict__ rm1, const float* __restrict__ rv1,
    const float* __restrict__ bng, const float* __restrict__ bnb,
    const float* __restrict__ bnrm, const float* __restrict__ bnrv,
    const float* __restrict__ W1, const float* __restrict__ W2) {
    int b = blockIdx.x, tid = threadIdx.x;
    if (b < 3200) {
        const float4* x4 = (const float4*)x;
#pragma unroll
        for (int i = 0; i < 4; i++) {
            int idx = (b * 256 + tid) * 4 + i;
            if (idx < NN * 32) {
                float4 v = x4[idx];
                g_x16[idx] = make_uint2(packh2(v.x, v.y), packh2(v.z, v.w));
            }
        }
    } else if (b < 3591) {
        int i = (b - 3200) * 256 + tid;
        if (i < NN) g_deg[i] = 0;
    } else if (b < 3593) {
        int t = (b - 3591) * 256 + tid;   // 0..511
        if (t < LL * HH) {
            float a = g1[t] * rsqrtf(rv1[t] + BN_EPS);
            g_a1[t] = a;
            g_c1[t] = beta1[t] - a * rm1[t];
        }
        if (t < HH) {
            float a = bng[t] * rsqrtf(bnrv[t] + BN_EPS);
            g_ap[t] = a;
            g_cp[t] = bnb[t] - a * bnrm[t];
        }
        int lo = 0, hi = NN;
        while (lo < hi) { int m = (lo + hi) >> 1; if (batch[m] < t) lo = m + 1; else hi = m; }
        g_gst[t] = lo;
        if (t == 0) g_gst[GG] = NN;
    } else {
        int mat = b - 3593;   // 0..5
        int l = mat >> 1, ph = mat & 1;
        const float* w = (ph ? W2 : W1) + l * HH * HH;
        uint2* outp = &g_wb[mat * 4096];
#pragma unroll
        for (int i = 0; i < 16; i++) {
            int s = tid + i * 256;
            int nt = s >> 8, ks = (s >> 5) & 7, lane = s & 31;
            int k0 = ks * 16 + (lane & 3) * 2;
            int n = nt * 8 + (lane >> 2);
            outp[s] = make_uint2(packh2(w[k0 * HH + n], w[(k0 + 1) * HH + n]),
                                 packh2(w[(k0 + 8) * HH + n], w[(k0 + 9) * HH + n]));
        }
    }
}

// ---------------- CSR build ----------------
__global__ void k_hist_deg(const int* __restrict__ dst) {
    int i = blockIdx.x * blockDim.x + threadIdx.x;
    if (i < EE) atomicAdd(&g_deg[dst[i]], 1);
}

__global__ void k_scan1() {
    __shared__ int sm[1024];
    int t = threadIdx.x;
    int i = blockIdx.x * 1024 + t;
    int v = (i < NN) ? g_deg[i] : 0;
    sm[t] = v;
    __syncthreads();
    for (int off = 1; off < 1024; off <<= 1) {
        int u = (t >= off) ? sm[t - off] : 0;
        __syncthreads();
        sm[t] += u;
        __syncthreads();
    }
    if (i < NN) g_incl[i] = sm[t];
    if (t == 1023) g_bsum[blockIdx.x] = sm[1023];
}

__global__ void k_scan_bsum() {
    __shared__ int sm[128];
    int t = threadIdx.x;
    const int nb = (NN + 1023) / 1024;
    int v = (t < nb) ? g_bsum[t] : 0;
    sm[t] = v;
    __syncthreads();
    for (int off = 1; off < 128; off <<= 1) {
        int u = (t >= off) ? sm[t - off] : 0;
        __syncthreads();
        sm[t] += u;
        __syncthreads();
    }
    g_boff[t] = sm[t] - v;
}

__global__ void k_finalize_rs() {
    int i = blockIdx.x * blockDim.x + threadIdx.x;
    if (i < NN) {
        int incl = g_incl[i] + g_boff[i >> 10];
        g_rs[i + 1] = incl;
        g_cur[i] = incl - g_deg[i];
    }
    if (i == 0) g_rs[0] = 0;
}

__global__ void k_scatter(const int* __restrict__ src, const int* __restrict__ dst) {
    int e = blockIdx.x * blockDim.x + threadIdx.x;
    if (e < EE) {
        int p = atomicAdd(&g_cur[dst[e]], 1);
        g_col[p] = src[e];
    }
}

// ---------------- aggregation: warp per node, all fp16 ----------------
__global__ void __launch_bounds__(256) k_agg(int layer) {
    const uint2* __restrict__ h16 = (layer == 0) ? g_x16 : g_h16;
    int w = threadIdx.x >> 5, lane = threadIdx.x & 31;
    int node = blockIdx.x * 8 + w;
    if (node >= NN) return;
    int beg = g_rs[node], end = g_rs[node + 1];
    uint2 sv = h16[node * 32 + lane];
    float2 f0 = __half22float2(*(__half2*)&sv.x);
    float2 f1 = __half22float2(*(__half2*)&sv.y);
    float a0 = f0.x, a1 = f0.y, a2 = f1.x, a3 = f1.y;
    for (int j = beg; j < end; j += 32) {
        int cnt = min(32, end - j);
        int idx = (lane < cnt) ? g_col[j + lane] : 0;
        int u = 0;
        for (; u + 4 <= cnt; u += 4) {
            int j0 = __shfl_sync(0xffffffffu, idx, u);
            int j1 = __shfl_sync(0xffffffffu, idx, u + 1);
            int j2 = __shfl_sync(0xffffffffu, idx, u + 2);
            int j3 = __shfl_sync(0xffffffffu, idx, u + 3);
            uint2 v0 = h16[j0 * 32 + lane];
            uint2 v1 = h16[j1 * 32 + lane];
            uint2 v2 = h16[j2 * 32 + lane];
            uint2 v3 = h16[j3 * 32 + lane];
            float2 f;
            f = __half22float2(*(__half2*)&v0.x); a0 += f.x; a1 += f.y;
            f = __half22float2(*(__half2*)&v0.y); a2 += f.x; a3 += f.y;
            f = __half22float2(*(__half2*)&v1.x); a0 += f.x; a1 += f.y;
            f = __half22float2(*(__half2*)&v1.y); a2 += f.x; a3 += f.y;
            f = __half22float2(*(__half2*)&v2.x); a0 += f.x; a1 += f.y;
            f = __half22float2(*(__half2*)&v2.y); a2 += f.x; a3 += f.y;
            f = __half22float2(*(__half2*)&v3.x); a0 += f.x; a1 += f.y;
            f = __half22float2(*(__half2*)&v3.y); a2 += f.x; a3 += f.y;
        }
        for (; u < cnt; u++) {
            int jj = __shfl_sync(0xffffffffu, idx, u);
            uint2 v = h16[jj * 32 + lane];
            float2 f;
            f = __half22float2(*(__half2*)&v.x); a0 += f.x; a1 += f.y;
            f = __half22float2(*(__half2*)&v.y); a2 += f.x; a3 += f.y;
        }
    }
    g_s16[node * 32 + lane] = make_uint2(packh2(a0, a1), packh2(a2, a3));
}

// ---------------- fused MLP, fp16 single-term HMMA ----------------
// smem: As uint4[2048] 32KB @0 ; B1 uint2[4096] 32KB @32KB ; B2 @64KB = 96KB
__global__ void __launch_bounds__(256, 2) k_mlp(const float* __restrict__ b1,
                                                const float* __restrict__ b2, int l) {
    extern __shared__ char sm[];
    uint4* As = (uint4*)sm;
    uint2* Bs1 = (uint2*)(sm + 32768);
    uint2* Bs2 = (uint2*)(sm + 65536);

    int tid = threadIdx.x, wid = tid >> 5, lane = tid & 31;
    int warp_m = wid >> 2, warp_n = wid & 3;
    int m0 = blockIdx.x * 128;

    // both weight images: 64KB contiguous
    {
        const uint4* src = (const uint4*)&g_wb[l * 8192];
        uint4* dst = (uint4*)Bs1;
#pragma unroll
        for (int i = 0; i < 16; i++) dst[tid + i * 256] = src[tid + i * 256];
    }

    // A: fp16 repack into fragment layout
    const uint32_t* __restrict__ S32 = (const uint32_t*)g_s16;
#pragma unroll
    for (int i = 0; i < 8; i++) {
        int s = tid + i * 256;
        int mt = s >> 8, ks = (s >> 5) & 7, ln = s & 31;
        int r = m0 + mt * 16 + (ln >> 2);
        int cp = ks * 8 + (ln & 3);
        uint4 a = make_uint4(0u, 0u, 0u, 0u);
        if (r < NN)     { a.x = S32[r * 64 + cp];       a.z = S32[r * 64 + cp + 4]; }
        if (r + 8 < NN) { a.y = S32[(r + 8) * 64 + cp]; a.w = S32[(r + 8) * 64 + cp + 4]; }
        As[s] = a;
    }
    __syncthreads();

    float d[4][4][4];
#pragma unroll
    for (int mt = 0; mt < 4; mt++)
#pragma unroll
        for (int nt = 0; nt < 4; nt++)
#pragma unroll
            for (int q = 0; q < 4; q++) d[mt][nt][q] = 0.f;

    // ---- GEMM1 ----
#pragma unroll 1
    for (int ks = 0; ks < 8; ks++) {
        uint4 ah[4];
#pragma unroll
        for (int mt = 0; mt < 4; mt++)
            ah[mt] = As[((warp_m * 4 + mt) * 8 + ks) * 32 + lane];
#pragma unroll
        for (int nt = 0; nt < 4; nt++) {
            uint2 bh = Bs1[((warp_n * 4 + nt) * 8 + ks) * 32 + lane];
#pragma unroll
            for (int mt = 0; mt < 4; mt++) mma_f16(d[mt][nt], ah[mt], bh);
        }
    }

    // ---- epilogue1 -> GEMM2 A-fragments (in-register) ----
    uint4 tf[4][2];
    {
        float aa[8], cc[8], bb[8];
#pragma unroll
        for (int j = 0; j < 8; j++) {
            int c = warp_n * 32 + (j >> 1) * 8 + (lane & 3) * 2 + (j & 1);
            bb[j] = b1[c];
            aa[j] = g_a1[l * HH + c];
            cc[j] = g_c1[l * HH + c];
        }
#pragma unroll
        for (int mt = 0; mt < 4; mt++) {
#pragma unroll
            for (int nt = 0; nt < 4; nt++) {
#pragma unroll
                for (int q = 0; q < 4; q++) {
                    float v = d[mt][nt][q] + bb[nt * 2 + (q & 1)];
                    v = v > 0.f ? v : SLOPE * v;
                    d[mt][nt][q] = aa[nt * 2 + (q & 1)] * v + cc[nt * 2 + (q & 1)];
                }
            }
#pragma unroll
            for (int kp = 0; kp < 2; kp++) {
                tf[mt][kp].x = packh2(d[mt][2 * kp][0],     d[mt][2 * kp][1]);
                tf[mt][kp].y = packh2(d[mt][2 * kp][2],     d[mt][2 * kp][3]);
                tf[mt][kp].z = packh2(d[mt][2 * kp + 1][0], d[mt][2 * kp + 1][1]);
                tf[mt][kp].w = packh2(d[mt][2 * kp + 1][2], d[mt][2 * kp + 1][3]);
            }
        }
    }
    __syncthreads();
#pragma unroll
    for (int mt = 0; mt < 4; mt++)
#pragma unroll
        for (int kp = 0; kp < 2; kp++)
            As[((warp_m * 4 + mt) * 8 + warp_n * 2 + kp) * 32 + lane] = tf[mt][kp];
    __syncthreads();

#pragma unroll
    for (int mt = 0; mt < 4; mt++)
#pragma unroll
        for (int nt = 0; nt < 4; nt++)
#pragma unroll
            for (int q = 0; q < 4; q++) d[mt][nt][q] = 0.f;

    // ---- GEMM2 ----
#pragma unroll 1
    for (int ks = 0; ks < 8; ks++) {
        uint4 ah[4];
#pragma unroll
        for (int mt = 0; mt < 4; mt++)
            ah[mt] = As[((warp_m * 4 + mt) * 8 + ks) * 32 + lane];
#pragma unroll
        for (int nt = 0; nt < 4; nt++) {
            uint2 bh = Bs2[((warp_n * 4 + nt) * 8 + ks) * 32 + lane];
#pragma unroll
            for (int mt = 0; mt < 4; mt++) mma_f16(d[mt][nt], ah[mt], bh);
        }
    }

    // ---- epilogue2: bias + leaky -> g_h16 ----
    uint32_t* __restrict__ H32 = (uint32_t*)g_h16;
#pragma unroll
    for (int nt = 0; nt < 4; nt++) {
        int c0 = warp_n * 32 + nt * 8 + (lane & 3) * 2;
        float bb0 = b2[c0], bb1 = b2[c0 + 1];
#pragma unroll
        for (int mt = 0; mt < 4; mt++) {
            int r = m0 + warp_m * 64 + mt * 16 + (lane >> 2);
            float v0 = d[mt][nt][0] + bb0, v1 = d[mt][nt][1] + bb1;
            float v2 = d[mt][nt][2] + bb0, v3 = d[mt][nt][3] + bb1;
            v0 = v0 > 0.f ? v0 : SLOPE * v0;
            v1 = v1 > 0.f ? v1 : SLOPE * v1;
            v2 = v2 > 0.f ? v2 : SLOPE * v2;
            v3 = v3 > 0.f ? v3 : SLOPE * v3;
            if (r < NN)     H32[r * 64 + c0 / 2]       = packh2(v0, v1);
            if (r + 8 < NN) H32[(r + 8) * 64 + c0 / 2] = packh2(v2, v3);
        }
    }
}

// ---------------- pooling + pooled-BN + FC (64 threads/graph) ----------------
__global__ void __launch_bounds__(64) k_pool(const float* __restrict__ fcW,
                                             const float* __restrict__ fcb,
                                             float* __restrict__ out) {
    int g = blockIdx.x, t = threadIdx.x;  // t<64: col pair 2t,2t+1
    int beg = g_gst[g], end = g_gst[g + 1];
    const uint32_t* __restrict__ H32 = (const uint32_t*)g_h16;
    float a0 = 0.f, a1 = 0.f;
    for (int i = beg; i < end; i++) {
        uint32_t v = H32[i * 64 + t];
        float2 f = __half22float2(*(__half2*)&v);
        a0 += f.x; a1 += f.y;
    }
    __shared__ float p[128];
    p[2 * t]     = g_ap[2 * t] * a0 + g_cp[2 * t];
    p[2 * t + 1] = g_ap[2 * t + 1] * a1 + g_cp[2 * t + 1];
    __syncthreads();
    float o = fcb[t];
#pragma unroll 4
    for (int k = 0; k < HH; k++) o += p[k] * fcW[k * LAT + t];
    out[g * LAT + t] = o;
}

// ---------------- launcher ----------------
extern "C" void kernel_launch(void* const* d_in, const int* in_sizes, int n_in,
                              void* d_out, int out_size) {
    const float* x     = (const float*)d_in[0];
    const int*   ei    = (const int*)d_in[1];
    const int*   batch = (const int*)d_in[2];
    const float* W1    = (const float*)d_in[3];
    const float* b1    = (const float*)d_in[4];
    const float* g1    = (const float*)d_in[5];
    const float* beta1 = (const float*)d_in[6];
    const float* rm1   = (const float*)d_in[7];
    const float* rv1   = (const float*)d_in[8];
    const float* W2    = (const float*)d_in[9];
    const float* b2    = (const float*)d_in[10];
    const float* bng   = (const float*)d_in[11];
    const float* bnb   = (const float*)d_in[12];
    const float* bnrm  = (const float*)d_in[13];
    const float* bnrv  = (const float*)d_in[14];
    const float* fcW   = (const float*)d_in[15];
    const float* fcb   = (const float*)d_in[16];
    float* out = (float*)d_out;
    const int* src = ei;
    const int* dst = ei + EE;

    const int smem = 98304;
    cudaFuncSetAttribute(k_mlp, cudaFuncAttributeMaxDynamicSharedMemorySize, smem);

    k_setup<<<3599, 256>>>(x, batch, g1, beta1, rm1, rv1, bng, bnb, bnrm, bnrv, W1, W2);
    k_hist_deg<<<(EE + 255) / 256, 256>>>(dst);
    k_scan1<<<(NN + 1023) / 1024, 1024>>>();
    k_scan_bsum<<<1, 128>>>();
    k_finalize_rs<<<(NN + 255) / 256, 256>>>();
    k_scatter<<<(EE + 255) / 256, 256>>>(src, dst);

    const int gb = (NN + 127) / 128;   // 782
    for (int l = 0; l < LL; l++) {
        k_agg<<<(NN + 7) / 8, 256>>>(l);
        k_mlp<<<gb, 256, smem>>>(b1 + l * HH, b2 + l * HH, l);
    }
    k_pool<<<GG, 64>>>(fcW, fcb, out);
}